// round 4
// baseline (speedup 1.0000x reference)
#include <cuda_runtime.h>
#include <cstdint>

// Bloom filter: NUM_BITS = 2^27, NUM_HASHES = 7, PRIME = 2654435761.
// Positions for value v: (v*PRIME + s) & (2^27-1), s=0..6 -> 7 CONSECUTIVE
// bits starting at h = (v*PRIME) & MASK. Low 27 bits of the int64 product
// equal those of the 32-bit wrapping product (v < 2^31): one IMAD per hash.
//
// Inputs may be stored as int64 or canonicalized int32 — detected on device
// (high words all-zero over 4096 pairs <=> 8-byte storage). Output: float32.

#define NUM_BITS   (1u << 27)
#define BIT_MASK   (NUM_BITS - 1u)
#define PRIME      2654435761u
#define NUM_WORDS  (NUM_BITS / 64u)        // 2^21 x u64 = 16 MB (L2-resident)
#define WORD_MASK  (NUM_WORDS - 1u)

__device__ unsigned long long g_bits[NUM_WORDS];
__device__ int g_wide;   // 1 -> 8-byte input storage, 0 -> 4-byte

// --------------------------------------------------- clear (+ detect) ----
// Exact-fit: 1024 blocks x 256 threads x 4 ulonglong2 = 2^20 chunks = 16 MB.
__global__ void __launch_bounds__(256) clear_kernel(const int* __restrict__ a) {
    if (blockIdx.x == 0) {
        __shared__ int s_any;
        if (threadIdx.x == 0) s_any = 0;
        __syncthreads();
        int acc = 0;
        #pragma unroll
        for (int k = 0; k < 16; ++k)
            acc |= a[2 * (threadIdx.x + 256 * k) + 1];
        if (acc) atomicOr(&s_any, 1);
        __syncthreads();
        if (threadIdx.x == 0) g_wide = (s_any == 0) ? 1 : 0;
    }
    ulonglong2* p = reinterpret_cast<ulonglong2*>(g_bits);
    const ulonglong2 z = make_ulonglong2(0ull, 0ull);
    unsigned int t = blockIdx.x * 256u + threadIdx.x;   // 2^18 threads
    #pragma unroll
    for (int k = 0; k < 4; ++k)
        p[t + (unsigned)k * (1u << 18)] = z;
}

// ---------------------------------------------------------------- add ----
__device__ __forceinline__ void do_add(unsigned int v) {
    unsigned int pos = (v * PRIME) & BIT_MASK;
    unsigned int w   = pos >> 6;
    unsigned int b   = pos & 63u;
    atomicOr(&g_bits[w], 0x7Full << b);           // bits >=64 shift out
    if (b > 57u)
        atomicOr(&g_bits[(w + 1u) & WORD_MASK], 0x7Full >> (64u - b));
}

// 8 values per thread.
__global__ void __launch_bounds__(256) add_kernel(const int* __restrict__ vals, int n) {
    int base = (blockIdx.x * blockDim.x + threadIdx.x) * 8;
    if (base + 7 < n) {
        unsigned int v[8];
        if (g_wide) {
            #pragma unroll
            for (int k = 0; k < 4; ++k) {
                int4 a = *reinterpret_cast<const int4*>(vals + 2 * base + 4 * k);
                v[2 * k] = (unsigned)a.x; v[2 * k + 1] = (unsigned)a.z;
            }
        } else {
            #pragma unroll
            for (int k = 0; k < 2; ++k) {
                int4 a = *reinterpret_cast<const int4*>(vals + base + 4 * k);
                v[4 * k] = (unsigned)a.x; v[4 * k + 1] = (unsigned)a.y;
                v[4 * k + 2] = (unsigned)a.z; v[4 * k + 3] = (unsigned)a.w;
            }
        }
        #pragma unroll
        for (int k = 0; k < 8; ++k) do_add(v[k]);
    } else {
        const int stride = g_wide ? 2 : 1;
        for (int i = base; i < n; ++i) do_add((unsigned)vals[i * stride]);
    }
}

// -------------------------------------------------------------- query ----
__device__ __forceinline__ float do_query(unsigned int v) {
    unsigned int pos = (v * PRIME) & BIT_MASK;
    unsigned int c   = pos >> 7;                  // 128-bit chunk
    unsigned int t   = pos & 127u;
    const ulonglong2* p2 = reinterpret_cast<const ulonglong2*>(g_bits);
    ulonglong2 B = __ldg(&p2[c]);
    unsigned long long lo = (t & 64u) ? B.y : B.x;
    unsigned int s = t & 63u;
    unsigned long long field = lo >> s;
    if (s > 57u) {                                // field straddles 'lo'
        unsigned long long hi;
        if (t & 64u) hi = __ldg(&g_bits[(2u * c + 2u) & WORD_MASK]);  // 4.7%
        else         hi = B.y;                                         // free
        field |= hi << (64u - s);
    }
    return ((field & 0x7Full) == 0x7Full) ? 1.0f : 0.0f;
}

// 8 queries per thread: 8 independent gathers in flight.
__global__ void __launch_bounds__(256) query_kernel(const int* __restrict__ q,
                                                    float* __restrict__ out, int n) {
    int base = (blockIdx.x * blockDim.x + threadIdx.x) * 8;
    if (base + 7 < n) {
        unsigned int v[8];
        if (g_wide) {
            #pragma unroll
            for (int k = 0; k < 4; ++k) {
                int4 a = *reinterpret_cast<const int4*>(q + 2 * base + 4 * k);
                v[2 * k] = (unsigned)a.x; v[2 * k + 1] = (unsigned)a.z;
            }
        } else {
            #pragma unroll
            for (int k = 0; k < 2; ++k) {
                int4 a = *reinterpret_cast<const int4*>(q + base + 4 * k);
                v[4 * k] = (unsigned)a.x; v[4 * k + 1] = (unsigned)a.y;
                v[4 * k + 2] = (unsigned)a.z; v[4 * k + 3] = (unsigned)a.w;
            }
        }
        float r[8];
        #pragma unroll
        for (int k = 0; k < 8; ++k) r[k] = do_query(v[k]);
        float4 r0 = make_float4(r[0], r[1], r[2], r[3]);
        float4 r1 = make_float4(r[4], r[5], r[6], r[7]);
        *reinterpret_cast<float4*>(out + base)     = r0;
        *reinterpret_cast<float4*>(out + base + 4) = r1;
    } else {
        const int stride = g_wide ? 2 : 1;
        for (int i = base; i < n; ++i)
            out[i] = do_query((unsigned)q[i * stride]);
    }
}

// ----------------------------------------------------------- launcher ----
extern "C" void kernel_launch(void* const* d_in, const int* in_sizes, int n_in,
                              void* d_out, int out_size) {
    const int* add_values   = (const int*)d_in[0];
    const int* query_values = (const int*)d_in[1];
    float*     out          = (float*)d_out;
    int n_add = in_sizes[0];
    int n_qry = in_sizes[1];

    clear_kernel<<<1024, 256>>>(add_values);
    add_kernel<<<(n_add + 2047) / 2048, 256>>>(add_values, n_add);
    query_kernel<<<(n_qry + 2047) / 2048, 256>>>(query_values, out, n_qry);
}

// round 5
// speedup vs baseline: 1.0343x; 1.0343x over previous
#include <cuda_runtime.h>
#include <cstdint>

// Bloom filter: NUM_BITS = 2^27, NUM_HASHES = 7, PRIME = 2654435761.
// Positions for value v: (v*PRIME + s) & (2^27-1), s=0..6 -> 7 CONSECUTIVE
// bits starting at h = (v*PRIME) & MASK. Low 27 bits of the int64 product
// equal those of the 32-bit wrapping product (v < 2^31): one IMAD per hash.
//
// Inputs may be stored as int64 or canonicalized int32 — detected on device
// (high words all-zero over 128 pairs <=> 8-byte storage). Output: float32.

#define NUM_BITS   (1u << 27)
#define BIT_MASK   (NUM_BITS - 1u)
#define PRIME      2654435761u
#define NUM_WORDS  (NUM_BITS / 64u)        // 2^21 x u64 = 16 MB (L2-resident)
#define WORD_MASK  (NUM_WORDS - 1u)

__device__ unsigned long long g_bits[NUM_WORDS];
__device__ int g_wide;   // 1 -> 8-byte input storage, 0 -> 4-byte

// --------------------------------------------------------------- detect ----
__global__ void detect_kernel(const int* __restrict__ a) {
    // one warp, 128 high-words; all-zero <=> int64 storage
    unsigned int acc = 0;
    #pragma unroll
    for (int k = 0; k < 4; ++k)
        acc |= (unsigned)a[2 * (threadIdx.x + 32 * k) + 1];
    acc = __reduce_or_sync(0xFFFFFFFFu, acc);
    if (threadIdx.x == 0) g_wide = (acc == 0u) ? 1 : 0;
}

// ------------------------------------------------------------------ add ----
__device__ __forceinline__ void do_add(unsigned int v) {
    unsigned int pos = (v * PRIME) & BIT_MASK;
    unsigned int w   = pos >> 6;
    unsigned int b   = pos & 63u;
    atomicOr(&g_bits[w], 0x7Full << b);           // bits >=64 shift out
    if (b > 57u)
        atomicOr(&g_bits[(w + 1u) & WORD_MASK], 0x7Full >> (64u - b));
}

// 4 values per thread (R3 sweet spot).
__global__ void __launch_bounds__(256) add_kernel(const int* __restrict__ vals, int n) {
    int base = (blockIdx.x * blockDim.x + threadIdx.x) * 4;
    if (base + 3 < n) {
        unsigned int v0, v1, v2, v3;
        if (g_wide) {
            int4 a = *reinterpret_cast<const int4*>(vals + 2 * base);
            int4 b = *reinterpret_cast<const int4*>(vals + 2 * base + 4);
            v0 = (unsigned)a.x; v1 = (unsigned)a.z;
            v2 = (unsigned)b.x; v3 = (unsigned)b.z;
        } else {
            int4 a = *reinterpret_cast<const int4*>(vals + base);
            v0 = (unsigned)a.x; v1 = (unsigned)a.y;
            v2 = (unsigned)a.z; v3 = (unsigned)a.w;
        }
        do_add(v0); do_add(v1); do_add(v2); do_add(v3);
    } else {
        const int stride = g_wide ? 2 : 1;
        for (int i = base; i < n; ++i) do_add((unsigned)vals[i * stride]);
    }
}

// ---------------------------------------------------------------- query ----
__device__ __forceinline__ float do_query(unsigned int v) {
    unsigned int pos = (v * PRIME) & BIT_MASK;
    unsigned int c   = pos >> 7;                  // 128-bit chunk
    unsigned int t   = pos & 127u;
    const ulonglong2* p2 = reinterpret_cast<const ulonglong2*>(g_bits);
    ulonglong2 B = __ldg(&p2[c]);
    unsigned long long lo = (t & 64u) ? B.y : B.x;
    unsigned int s = t & 63u;
    unsigned long long field = lo >> s;
    if (s > 57u) {                                // field straddles 'lo'
        unsigned long long hi;
        if (t & 64u) hi = __ldg(&g_bits[(2u * c + 2u) & WORD_MASK]);  // 4.7%
        else         hi = B.y;                                         // free
        field |= hi << (64u - s);
    }
    return ((field & 0x7Full) == 0x7Full) ? 1.0f : 0.0f;
}

// 4 queries per thread (R3 sweet spot).
__global__ void __launch_bounds__(256) query_kernel(const int* __restrict__ q,
                                                    float* __restrict__ out, int n) {
    int base = (blockIdx.x * blockDim.x + threadIdx.x) * 4;
    if (base + 3 < n) {
        unsigned int v0, v1, v2, v3;
        if (g_wide) {
            int4 a = *reinterpret_cast<const int4*>(q + 2 * base);
            int4 b = *reinterpret_cast<const int4*>(q + 2 * base + 4);
            v0 = (unsigned)a.x; v1 = (unsigned)a.z;
            v2 = (unsigned)b.x; v3 = (unsigned)b.z;
        } else {
            int4 a = *reinterpret_cast<const int4*>(q + base);
            v0 = (unsigned)a.x; v1 = (unsigned)a.y;
            v2 = (unsigned)a.z; v3 = (unsigned)a.w;
        }
        float4 r;
        r.x = do_query(v0); r.y = do_query(v1);
        r.z = do_query(v2); r.w = do_query(v3);
        *reinterpret_cast<float4*>(out + base) = r;
    } else {
        const int stride = g_wide ? 2 : 1;
        for (int i = base; i < n; ++i)
            out[i] = do_query((unsigned)q[i * stride]);
    }
}

// ------------------------------------------------------------- launcher ----
extern "C" void kernel_launch(void* const* d_in, const int* in_sizes, int n_in,
                              void* d_out, int out_size) {
    const int* add_values   = (const int*)d_in[0];
    const int* query_values = (const int*)d_in[1];
    float*     out          = (float*)d_out;
    int n_add = in_sizes[0];
    int n_qry = in_sizes[1];

    // Clear via driver memset (graph-capturable, no allocation).
    void* bits_ptr = nullptr;
    cudaGetSymbolAddress(&bits_ptr, g_bits);
    cudaMemsetAsync(bits_ptr, 0, NUM_WORDS * sizeof(unsigned long long));

    detect_kernel<<<1, 32>>>(add_values);
    add_kernel<<<(n_add + 1023) / 1024, 256>>>(add_values, n_add);
    query_kernel<<<(n_qry + 1023) / 1024, 256>>>(query_values, out, n_qry);
}

// round 6
// speedup vs baseline: 1.0664x; 1.0310x over previous
#include <cuda_runtime.h>
#include <cstdint>

// Bloom filter: NUM_BITS = 2^27, NUM_HASHES = 7, PRIME = 2654435761.
// Positions for value v: (v*PRIME + s) & (2^27-1), s=0..6 -> 7 CONSECUTIVE
// bits starting at h = (v*PRIME) & MASK. Low 27 bits of the int64 product
// equal those of the 32-bit wrapping product (v < 2^31): one IMAD per hash.
//
// Input storage (int64 vs canonicalized int32) is detected PER-THREAD from
// the first 8 ints of the array (uniform L1-broadcast load): wide storage
// <=> odd words all zero (P[false positive] = 2^-124 for random int32 data).
// Output: float32.

#define NUM_BITS   (1u << 27)
#define BIT_MASK   (NUM_BITS - 1u)
#define PRIME      2654435761u
#define NUM_WORDS  (NUM_BITS / 64u)        // 2^21 x u64 = 16 MB (L2-resident)
#define WORD_MASK  (NUM_WORDS - 1u)

__device__ unsigned long long g_bits[NUM_WORDS];

// ---------------------------------------------------------------- probe ----
// Uniform-address probe: all threads read the same 32 bytes (broadcast).
__device__ __forceinline__ bool probe_wide(const int* __restrict__ p) {
    int4 a = __ldg(reinterpret_cast<const int4*>(p));
    int4 b = __ldg(reinterpret_cast<const int4*>(p) + 1);
    return ((a.y | a.w | b.y | b.w) == 0);
}

// ------------------------------------------------------------------ add ----
__device__ __forceinline__ void do_add(unsigned int v) {
    unsigned int pos = (v * PRIME) & BIT_MASK;
    unsigned int w   = pos >> 6;
    unsigned int b   = pos & 63u;
    atomicOr(&g_bits[w], 0x7Full << b);           // bits >=64 shift out
    if (b > 57u)
        atomicOr(&g_bits[(w + 1u) & WORD_MASK], 0x7Full >> (64u - b));
}

// 4 values per thread.
__global__ void __launch_bounds__(256) add_kernel(const int* __restrict__ vals, int n) {
    const bool wide = probe_wide(vals);
    int base = (blockIdx.x * blockDim.x + threadIdx.x) * 4;
    if (base + 3 < n) {
        unsigned int v0, v1, v2, v3;
        if (wide) {
            int4 a = *reinterpret_cast<const int4*>(vals + 2 * base);
            int4 b = *reinterpret_cast<const int4*>(vals + 2 * base + 4);
            v0 = (unsigned)a.x; v1 = (unsigned)a.z;
            v2 = (unsigned)b.x; v3 = (unsigned)b.z;
        } else {
            int4 a = *reinterpret_cast<const int4*>(vals + base);
            v0 = (unsigned)a.x; v1 = (unsigned)a.y;
            v2 = (unsigned)a.z; v3 = (unsigned)a.w;
        }
        do_add(v0); do_add(v1); do_add(v2); do_add(v3);
    } else {
        const int stride = wide ? 2 : 1;
        for (int i = base; i < n; ++i) do_add((unsigned)vals[i * stride]);
    }
}

// ---------------------------------------------------------------- query ----
__device__ __forceinline__ float do_query(unsigned int v) {
    unsigned int pos = (v * PRIME) & BIT_MASK;
    unsigned int c   = pos >> 7;                  // 128-bit chunk
    unsigned int t   = pos & 127u;
    const ulonglong2* p2 = reinterpret_cast<const ulonglong2*>(g_bits);
    ulonglong2 B = __ldg(&p2[c]);
    unsigned long long lo = (t & 64u) ? B.y : B.x;
    unsigned int s = t & 63u;
    unsigned long long field = lo >> s;
    if (s > 57u) {                                // field straddles 'lo'
        unsigned long long hi;
        if (t & 64u) hi = __ldg(&g_bits[(2u * c + 2u) & WORD_MASK]);  // 4.7%
        else         hi = B.y;                                         // free
        field |= hi << (64u - s);
    }
    return ((field & 0x7Full) == 0x7Full) ? 1.0f : 0.0f;
}

// 4 queries per thread.
__global__ void __launch_bounds__(256) query_kernel(const int* __restrict__ q,
                                                    float* __restrict__ out, int n) {
    const bool wide = probe_wide(q);
    int base = (blockIdx.x * blockDim.x + threadIdx.x) * 4;
    if (base + 3 < n) {
        unsigned int v0, v1, v2, v3;
        if (wide) {
            int4 a = *reinterpret_cast<const int4*>(q + 2 * base);
            int4 b = *reinterpret_cast<const int4*>(q + 2 * base + 4);
            v0 = (unsigned)a.x; v1 = (unsigned)a.z;
            v2 = (unsigned)b.x; v3 = (unsigned)b.z;
        } else {
            int4 a = *reinterpret_cast<const int4*>(q + base);
            v0 = (unsigned)a.x; v1 = (unsigned)a.y;
            v2 = (unsigned)a.z; v3 = (unsigned)a.w;
        }
        float4 r;
        r.x = do_query(v0); r.y = do_query(v1);
        r.z = do_query(v2); r.w = do_query(v3);
        *reinterpret_cast<float4*>(out + base) = r;
    } else {
        const int stride = wide ? 2 : 1;
        for (int i = base; i < n; ++i)
            out[i] = do_query((unsigned)q[i * stride]);
    }
}

// ------------------------------------------------------------- launcher ----
extern "C" void kernel_launch(void* const* d_in, const int* in_sizes, int n_in,
                              void* d_out, int out_size) {
    const int* add_values   = (const int*)d_in[0];
    const int* query_values = (const int*)d_in[1];
    float*     out          = (float*)d_out;
    int n_add = in_sizes[0];
    int n_qry = in_sizes[1];

    // Clear via driver memset (graph-capturable, no allocation).
    void* bits_ptr = nullptr;
    cudaGetSymbolAddress(&bits_ptr, g_bits);
    cudaMemsetAsync(bits_ptr, 0, NUM_WORDS * sizeof(unsigned long long));

    add_kernel<<<(n_add + 1023) / 1024, 256>>>(add_values, n_add);
    query_kernel<<<(n_qry + 1023) / 1024, 256>>>(query_values, out, n_qry);
}